// round 12
// baseline (speedup 1.0000x reference)
#include <cuda_runtime.h>
#include <math.h>

// Problem constants (from reference): T=128, B=4096, NOBS=32
#define T_DIM   128
#define B_DIM   4096
#define NOBS    32
#define LOG_2PI 1.8378770664093453

#define NTHREADS 256
#define NB_CACHED 888     // 6 CTAs per SM -> process resident 3/4 (L2-served)
#define NB_STREAM 296     // 2 CTAs per SM -> process streamed 1/4 (__ldcs, DRAM)
#define NBLOCKS   (NB_CACHED + NB_STREAM)   // 1184 = 8 per SM, one wave

// Scratch (device globals; no allocation allowed).
__device__ float        g_partials[NBLOCKS];
__device__ unsigned int g_count;

__device__ __forceinline__ float softplus_f(float x) {
    return fmaxf(x, 0.0f) + log1pf(expf(-fabsf(x)));
}

// Accumulate over [base, end) with region-local tid and stride. STREAM selects
// evict-first (__ldcs) loads. Region base and stride are multiples of 8
// float4-groups, so each thread's channel quad is fixed.
template <bool STREAM>
__device__ __forceinline__ float accum_region(const float4* __restrict__ Y,
                                              const float4* __restrict__ Yh,
                                              float iv0, float iv1, float iv2, float iv3,
                                              int base, int end, int rtid, int stride)
{
    float s = 0.0f;
    int g = base + rtid;
    for (; g + stride < end; g += 2 * stride) {
        float4 ya, yha, yb, yhb;
        if (STREAM) {
            ya  = __ldcs(&Y[g]);
            yha = __ldcs(&Yh[g]);
            yb  = __ldcs(&Y[g + stride]);
            yhb = __ldcs(&Yh[g + stride]);
        } else {
            ya  = Y[g];
            yha = Yh[g];
            yb  = Y[g + stride];
            yhb = Yh[g + stride];
        }
        float a0 = yha.x - ya.x, a1 = yha.y - ya.y, a2 = yha.z - ya.z, a3 = yha.w - ya.w;
        float b0 = yhb.x - yb.x, b1 = yhb.y - yb.y, b2 = yhb.z - yb.z, b3 = yhb.w - yb.w;
        s = fmaf(a0 * a0, iv0, s);
        s = fmaf(a1 * a1, iv1, s);
        s = fmaf(a2 * a2, iv2, s);
        s = fmaf(a3 * a3, iv3, s);
        s = fmaf(b0 * b0, iv0, s);
        s = fmaf(b1 * b1, iv1, s);
        s = fmaf(b2 * b2, iv2, s);
        s = fmaf(b3 * b3, iv3, s);
    }
    if (g < end) {
        float4 y, yh;
        if (STREAM) { y = __ldcs(&Y[g]); yh = __ldcs(&Yh[g]); }
        else        { y = Y[g];          yh = Yh[g]; }
        float d0 = yh.x - y.x, d1 = yh.y - y.y, d2 = yh.z - y.z, d3 = yh.w - y.w;
        s = fmaf(d0 * d0, iv0, s);
        s = fmaf(d1 * d1, iv1, s);
        s = fmaf(d2 * d2, iv2, s);
        s = fmaf(d3 * d3, iv3, s);
    }
    return s;
}

__global__ void __launch_bounds__(NTHREADS, 8)
elbo_kernel(const float4* __restrict__ Y,
            const float4* __restrict__ Yh,
            const float*  __restrict__ raw_sn,
            const float*  __restrict__ kl,
            const int*    __restrict__ Np,
            float* __restrict__ out,
            int n4)
{
    const int n4c = (n4 / 4) * 3;   // resident region size (multiple of 8)

    // Role partition: blocks [0, NB_CACHED) own the resident region,
    // blocks [NB_CACHED, NBLOCKS) own the streamed region; every SM gets
    // exactly 6 cached + 2 streaming CTAs.
    const bool cached_role = (blockIdx.x < NB_CACHED);
    const int  rbid   = cached_role ? blockIdx.x : (blockIdx.x - NB_CACHED);
    const int  rtid   = rbid * NTHREADS + threadIdx.x;
    const int  stride = (cached_role ? NB_CACHED : NB_STREAM) * NTHREADS; // % 8 == 0

    // fixed channel quad (region base and stride are multiples of 8 groups)
    const int c = (rtid & 7) * 4;
    const float iv0 = 1.0f / softplus_f(raw_sn[c + 0]);
    const float iv1 = 1.0f / softplus_f(raw_sn[c + 1]);
    const float iv2 = 1.0f / softplus_f(raw_sn[c + 2]);
    const float iv3 = 1.0f / softplus_f(raw_sn[c + 3]);

    float s = cached_role
        ? accum_region<false>(Y, Yh, iv0, iv1, iv2, iv3, 0,   n4c, rtid, stride)
        : accum_region<true >(Y, Yh, iv0, iv1, iv2, iv3, n4c, n4,  rtid, stride);

    // warp reduce
    #pragma unroll
    for (int off = 16; off > 0; off >>= 1)
        s += __shfl_down_sync(0xFFFFFFFFu, s, off);

    __shared__ float warp_sums[NTHREADS / 32];
    const int lane = threadIdx.x & 31;
    const int wid  = threadIdx.x >> 5;
    if (lane == 0) warp_sums[wid] = s;
    __syncthreads();

    __shared__ bool is_last;
    if (wid == 0) {
        float v = (lane < (NTHREADS >> 5)) ? warp_sums[lane] : 0.0f;
        #pragma unroll
        for (int off = 4; off > 0; off >>= 1)
            v += __shfl_down_sync(0xFFFFFFFFu, v, off);
        if (lane == 0) {
            g_partials[blockIdx.x] = v;
            __threadfence();
            unsigned int prev = atomicAdd(&g_count, 1u);
            is_last = (prev == (unsigned int)(NBLOCKS - 1));
        }
    }
    __syncthreads();

    if (!is_last) return;

    // ---- last block: final reduction (double) + epilogue ----
    double ds = 0.0;
    for (int i = threadIdx.x; i < NBLOCKS; i += NTHREADS)
        ds += (double)g_partials[i];

    #pragma unroll
    for (int off = 16; off > 0; off >>= 1)
        ds += __shfl_down_sync(0xFFFFFFFFu, ds, off);

    __shared__ double dwarp[NTHREADS / 32];
    if (lane == 0) dwarp[wid] = ds;
    __syncthreads();

    if (wid == 0) {
        double dv = (lane < (NTHREADS >> 5)) ? dwarp[lane] : 0.0;
        #pragma unroll
        for (int off = 4; off > 0; off >>= 1)
            dv += __shfl_down_sync(0xFFFFFFFFu, dv, off);

        float lv = logf(softplus_f(raw_sn[lane]));
        #pragma unroll
        for (int off = 16; off > 0; off >>= 1)
            lv += __shfl_down_sync(0xFFFFFFFFu, lv, off);

        if (lane == 0) {
            double S      = dv;
            double logdet = (double)lv;
            double Nd     = (double)(*Np);
            double res = 0.5 * Nd * (S / (double)B_DIM +
                                     (double)T_DIM * (logdet + (double)NOBS * LOG_2PI))
                       + (double)(*kl);
            out[0] = (float)res;
            g_count = 0;   // reset for next graph replay (deterministic)
        }
    }
}

extern "C" void kernel_launch(void* const* d_in, const int* in_sizes, int n_in,
                              void* d_out, int out_size)
{
    const float* Y      = (const float*)d_in[0];
    const float* Yh     = (const float*)d_in[1];
    const float* raw_sn = (const float*)d_in[2];
    const float* kl     = (const float*)d_in[3];
    const int*   Np     = (const int*)d_in[4];
    float* out = (float*)d_out;

    const int n4 = (T_DIM * B_DIM * NOBS) / 4;  // 4,194,304 float4 groups

    elbo_kernel<<<NBLOCKS, NTHREADS>>>((const float4*)Y, (const float4*)Yh,
                                       raw_sn, kl, Np, out, n4);
}